// round 13
// baseline (speedup 1.0000x reference)
#include <cuda_runtime.h>
#include <cstdint>

#define NGROUP 80
#define BEX 8
#define NPG 1024
#define MCENT 512
#define NTHR 512
#define MAXIT 300
#define TOLF 1e-3f
#define FINF __int_as_float(0x7f800000)

// ---------------- device globals (no allocation allowed) ----------------
__device__ unsigned int g_bar_count;   // packed: low 16 = arrivals, high = moved count; returns to 0
__device__ unsigned int g_bar_gen;     // monotonically increasing across replays (safe)
__device__ int g_notdone;              // published by last arriver before gen flip

// ---------------- threefry2x32 (exact JAX PRNG, partitionable scheme) ----------------
__device__ __forceinline__ uint32_t rotl32(uint32_t x, int d) { return (x << d) | (x >> (32 - d)); }

__device__ __forceinline__ void tf2x32(uint32_t k0, uint32_t k1, uint32_t x0, uint32_t x1,
                                       uint32_t& o0, uint32_t& o1) {
    uint32_t ks0 = k0, ks1 = k1, ks2 = k0 ^ k1 ^ 0x1BD11BDAu;
#define RND(r) { x0 += x1; x1 = rotl32(x1, r); x1 ^= x0; }
    x0 += ks0; x1 += ks1;
    RND(13) RND(15) RND(26) RND(6)   x0 += ks1; x1 += ks2 + 1u;
    RND(17) RND(29) RND(16) RND(24)  x0 += ks2; x1 += ks0 + 2u;
    RND(13) RND(15) RND(26) RND(6)   x0 += ks0; x1 += ks1 + 3u;
    RND(17) RND(29) RND(16) RND(24)  x0 += ks1; x1 += ks2 + 4u;
    RND(13) RND(15) RND(26) RND(6)   x0 += ks2; x1 += ks0 + 5u;
#undef RND
    o0 = x0; o1 = x1;
}

// starts[g] = jax.random.randint(key(1), (80,), 0, 1024)[g], partitionable threefry
__device__ __forceinline__ int jax_start(int gidx) {
    uint32_t c0, c1, o0, o1;
    tf2x32(0u, 1u, 0u, 1u, c0, c1);
    tf2x32(c0, c1, 0u, (uint32_t)gidx, o0, o1);
    return (int)((o0 ^ o1) & 1023u);
}

// ---------------- grid barrier with fused any-moved reduction ----------------
__device__ __forceinline__ int grid_barrier_any(int moved) {
    __shared__ int sNotdone;
    __syncthreads();
    if (threadIdx.x == 0) {
        volatile unsigned int* vgen = &g_bar_gen;
        unsigned int gen = *vgen;
        __threadfence();
        unsigned int ticket = atomicAdd(&g_bar_count, 1u + (moved ? 0x10000u : 0u));
        if ((ticket & 0xFFFFu) == NGROUP - 1) {
            unsigned int movedCnt = (ticket >> 16) + (moved ? 1u : 0u);
            g_bar_count = 0u;
            g_notdone = (movedCnt != 0u) ? 1 : 0;
            __threadfence();
            atomicAdd(&g_bar_gen, 1u);
        } else {
            while (*vgen == gen) { __nanosleep(32); }
        }
        __threadfence();
        sNotdone = *((volatile int*)&g_notdone);
    }
    __syncthreads();
    return sNotdone;
}

__device__ __forceinline__ float sq3(float a, float b, float c) {
    // ((a*a + b*b) + c*c), non-fused (reference-critical math)
    return __fadd_rn(__fadd_rn(__fmul_rn(a, a), __fmul_rn(b, b)), __fmul_rn(c, c));
}

// ---------------- main persistent kernel: FPS + k-means + score ----------------
__global__ void __launch_bounds__(NTHR, 1)
kmeans_kernel(const float* __restrict__ pos, float* __restrict__ out, int out_size) {
    __shared__ float4   sP[NPG];          // points                             16384 B
    __shared__ float4   sC[MCENT];        // centroids as (-2x,-2y,-2z,|c|^2)    8192 B
    __shared__ uint8_t  whist[32][MCENT]; // rows 0-15: A-points, 16-31: B      16384 B
    __shared__ uint16_t sortIdx[NPG];     // cluster-sorted point indices        2048 B
    __shared__ uint16_t sCnt[MCENT];
    __shared__ uint16_t sOff[MCENT];
    __shared__ uint32_t sWsum[16];
    __shared__ unsigned long long sSlot[MCENT];  // per-FPS-step argmax slots    4096 B
    __shared__ float    redF[16];
    __shared__ float    sScore;
    __shared__ int      sStart;

    const int g = blockIdx.x;
    const int t = threadIdx.x;
    const int b = g & (BEX - 1);           // group g = r*B + b  ->  example b
    const float* pb = pos + (size_t)b * NPG * 3;

    // two points per thread: A = t, B = t + 512
    const float pxA = pb[t * 3 + 0], pyA = pb[t * 3 + 1], pzA = pb[t * 3 + 2];
    const float pxB = pb[(t + NTHR) * 3 + 0], pyB = pb[(t + NTHR) * 3 + 1], pzB = pb[(t + NTHR) * 3 + 2];
    sP[t]        = make_float4(pxA, pyA, pzA, 0.f);
    sP[t + NTHR] = make_float4(pxB, pyB, pzB, 0.f);
    sSlot[t] = 0ull;                             // zero all 512 step slots once
    if (t == NTHR - 1) sStart = jax_start(g);    // merged starts kernel (exact)
    __syncthreads();

    const int wid = t >> 5, lane = t & 31;

    // ================= FPS init (R9-identical math; single-atomic reduction) =================
    int last = sStart;
    float mindA = FINF;
    float mindB = FINF;
    for (int k = 0; k < MCENT; ++k) {
        float4 q = sP[last];                   // uniform broadcast
        if (t == 0)
            sC[k] = make_float4(__fmul_rn(-2.0f, q.x), __fmul_rn(-2.0f, q.y),
                                __fmul_rn(-2.0f, q.z), sq3(q.x, q.y, q.z));
        {
            float dx = __fsub_rn(pxA, q.x), dy = __fsub_rn(pyA, q.y), dz = __fsub_rn(pzA, q.z);
            mindA = fminf(mindA, sq3(dx, dy, dz));
        }
        {
            float dx = __fsub_rn(pxB, q.x), dy = __fsub_rn(pyB, q.y), dz = __fsub_rn(pzB, q.z);
            mindB = fminf(mindB, sq3(dx, dy, dz));
        }
        // argmax(mind), FIRST-index tie-break. Packed key: (valbits << 10) | (1023 - idx);
        // positive-float bits monotonic; larger (1023-idx) == smaller idx among value ties.
        uint32_t bA = __float_as_uint(mindA);
        uint32_t bB = __float_as_uint(mindB);
        uint32_t val = (bB > bA) ? bB : bA;
        uint32_t idx = (bB > bA) ? (uint32_t)(t + NTHR) : (uint32_t)t;  // tie -> A (smaller idx)
        uint32_t inv = 1023u - idx;
        uint32_t wm  = __reduce_max_sync(0xffffffffu, val);
        uint32_t cnd = (val == wm) ? inv : 0u;
        uint32_t wiv = __reduce_max_sync(0xffffffffu, cnd);   // max inv = min idx among ties
        if (lane == 0)
            atomicMax(&sSlot[k], ((unsigned long long)wm << 10) | (unsigned long long)wiv);
        __syncthreads();   // all warps' atomics visible (CUDA shared-mem barrier semantics)
        unsigned long long r = sSlot[k];
        last = 1023 - (int)(r & 1023ull);      // decode smallest global index among maxima
    }
    __syncthreads();

    // ================= k-means loop (global lockstep; R9-verbatim) =================
    int bjA = 0, bjB = 0;
    for (int iter = 0; iter < MAXIT; ++iter) {
        // ---- assign: argmin_j (c2 + px*(-2cx) + py*(-2cy) + pz*(-2cz)) ----
        float bestA = FINF;
        float bestB = FINF;
        bjA = 0; bjB = 0;
        #pragma unroll 8
        for (int j = 0; j < MCENT; ++j) {
            float4 c = sC[j];
            float aA = __fmaf_rn(pzA, c.z, __fmaf_rn(pyA, c.y, __fmaf_rn(pxA, c.x, c.w)));
            float aB = __fmaf_rn(pzB, c.z, __fmaf_rn(pyB, c.y, __fmaf_rn(pxB, c.x, c.w)));
            if (aA < bestA) { bestA = aA; bjA = j; }   // strict '<' keeps first index
            if (aB < bestB) { bestB = aB; bjB = j; }
        }

        // ---- deterministic stable counting sort of points by cluster ----
        ((uint4*)whist)[t * 2]     = make_uint4(0u, 0u, 0u, 0u);   // zero 16KB
        ((uint4*)whist)[t * 2 + 1] = make_uint4(0u, 0u, 0u, 0u);
        __syncthreads();

        // per-warp stable ranks + per-warp histograms (A rows 0-15, B rows 16-31)
        uint32_t below = (1u << lane) - 1u;
        uint32_t mmA = __match_any_sync(0xffffffffu, (uint32_t)bjA);
        int riwA = __popc(mmA & below);
        if (riwA == 0) whist[wid][bjA] = (uint8_t)__popc(mmA);
        uint32_t mmB = __match_any_sync(0xffffffffu, (uint32_t)bjB);
        int riwB = __popc(mmB & below);
        if (riwB == 0) whist[16 + wid][bjB] = (uint8_t)__popc(mmB);
        __syncthreads();

        // per-cluster exclusive prefix over the 32 rows (in place) + counts
        uint32_t run = 0;
        #pragma unroll
        for (int w = 0; w < 32; ++w) {
            uint32_t v = whist[w][t];
            whist[w][t] = (uint8_t)run;
            run += v;
        }
        sCnt[t] = (uint16_t)run;

        // block-wide exclusive prefix sum over the 512 counts (16 warps)
        uint32_t x = run;
        #pragma unroll
        for (int o = 1; o < 32; o <<= 1) {
            uint32_t y = __shfl_up_sync(0xffffffffu, x, o);
            if (lane >= o) x += y;
        }
        uint32_t exclInWarp = x - run;
        if (lane == 31) sWsum[wid] = x;
        __syncthreads();
        if (wid == 0) {
            uint32_t wv = (lane < 16) ? sWsum[lane] : 0u;
            uint32_t xx = wv;
            #pragma unroll
            for (int o = 1; o < 16; o <<= 1) {
                uint32_t y = __shfl_up_sync(0xffffffffu, xx, o);
                if (lane >= o) xx += y;
            }
            if (lane < 16) sWsum[lane] = xx - wv;
        }
        __syncthreads();
        sOff[t] = (uint16_t)(sWsum[wid] + exclInWarp);
        __syncthreads();

        // scatter point indices; ascending-index order preserved per cluster
        {
            uint32_t rkA = (uint32_t)sOff[bjA] + whist[wid][bjA] + (uint32_t)riwA;
            sortIdx[rkA] = (uint16_t)t;
            uint32_t rkB = (uint32_t)sOff[bjB] + whist[16 + wid][bjB] + (uint32_t)riwB;
            sortIdx[rkB] = (uint16_t)(t + NTHR);
        }
        __syncthreads();

        // per-cluster ordered fold + centroid update + convergence
        int moved = 0;
        {
            uint32_t n = sCnt[t], base = sOff[t];
            float sx = 0.f, sy = 0.f, sz = 0.f;
            for (uint32_t k2 = 0; k2 < n; ++k2) {
                float4 p = sP[sortIdx[base + k2]];
                sx = __fadd_rn(sx, p.x);
                sy = __fadd_rn(sy, p.y);
                sz = __fadd_rn(sz, p.z);
            }
            float4 cs = sC[t];
            float ocx = __fmul_rn(-0.5f, cs.x);   // exact recovery
            float ocy = __fmul_rn(-0.5f, cs.y);
            float ocz = __fmul_rn(-0.5f, cs.z);
            float cntf = (float)n;
            float nx, ny, nz;
            if (n > 0) {
                nx = __fdiv_rn(sx, cntf); ny = __fdiv_rn(sy, cntf); nz = __fdiv_rn(sz, cntf);
            } else {
                nx = ocx; ny = ocy; nz = ocz;
            }
            float dx = __fsub_rn(ocx, nx), dy = __fsub_rn(ocy, ny), dz = __fsub_rn(ocz, nz);
            moved = !(sqrtf(sq3(dx, dy, dz)) < TOLF);
            sC[t] = make_float4(__fmul_rn(-2.0f, nx), __fmul_rn(-2.0f, ny),
                                __fmul_rn(-2.0f, nz), sq3(nx, ny, nz));
        }
        int any = __syncthreads_or(moved);
        int notdone = grid_barrier_any(any);
        if (!notdone) break;   // all blocks agree -> same iteration count everywhere
    }

    // ================= score: L1 to assigned (final) centroids =================
    {
        float4 ca = sC[bjA];
        float cax = __fmul_rn(-0.5f, ca.x), cay = __fmul_rn(-0.5f, ca.y), caz = __fmul_rn(-0.5f, ca.z);
        float4 cb = sC[bjB];
        float cbx = __fmul_rn(-0.5f, cb.x), cby = __fmul_rn(-0.5f, cb.y), cbz = __fmul_rn(-0.5f, cb.z);
        float s = fabsf(pxA - cax) + fabsf(pyA - cay) + fabsf(pzA - caz)
                + fabsf(pxB - cbx) + fabsf(pyB - cby) + fabsf(pzB - cbz);
        #pragma unroll
        for (int off = 16; off > 0; off >>= 1)
            s += __shfl_down_sync(0xffffffffu, s, off);
        if (lane == 0) redF[wid] = s;
        __syncthreads();
        if (wid == 0) {
            float v = (lane < 16) ? redF[lane] : 0.f;
            #pragma unroll
            for (int off = 8; off > 0; off >>= 1)
                v += __shfl_down_sync(0xffffffffu, v, off);
            if (lane == 0) sScore = v;
        }
        __syncthreads();
    }

    // ================= outputs: [classification | centroids | scores] =================
    int ci = g * NPG + t;
    if (ci < out_size) out[ci] = (float)bjA;
    int ci2 = g * NPG + NTHR + t;
    if (ci2 < out_size) out[ci2] = (float)bjB;
    {
        int base = NGROUP * NPG + g * (MCENT * 3) + t * 3;
        if (base + 2 < out_size) {
            float4 cs = sC[t];
            out[base + 0] = __fmul_rn(-0.5f, cs.x);
            out[base + 1] = __fmul_rn(-0.5f, cs.y);
            out[base + 2] = __fmul_rn(-0.5f, cs.z);
        }
    }
    if (t == 0) {
        int si = NGROUP * NPG + NGROUP * MCENT * 3 + g;
        if (si < out_size) out[si] = sScore;
    }
}

extern "C" void kernel_launch(void* const* d_in, const int* in_sizes, int n_in,
                              void* d_out, int out_size) {
    const float* pos = (const float*)d_in[0];
    kmeans_kernel<<<NGROUP, NTHR>>>(pos, (float*)d_out, out_size);
}

// round 14
// speedup vs baseline: 2.0330x; 2.0330x over previous
#include <cuda_runtime.h>
#include <cstdint>

#define NGROUP 80
#define BEX 8
#define NPG 1024
#define MCENT 512
#define NTHR 512
#define MAXIT 300
#define TOLF 1e-3f
#define FINF __int_as_float(0x7f800000)

// ---------------- device globals (no allocation allowed) ----------------
__device__ unsigned int g_bar_count;   // packed: low 16 = arrivals, high = moved count; returns to 0
__device__ unsigned int g_bar_gen;     // monotonically increasing across replays (safe)
__device__ int g_notdone;              // published by last arriver before gen flip

// ---------------- threefry2x32 (exact JAX PRNG, partitionable scheme) ----------------
__device__ __forceinline__ uint32_t rotl32(uint32_t x, int d) { return (x << d) | (x >> (32 - d)); }

__device__ __forceinline__ void tf2x32(uint32_t k0, uint32_t k1, uint32_t x0, uint32_t x1,
                                       uint32_t& o0, uint32_t& o1) {
    uint32_t ks0 = k0, ks1 = k1, ks2 = k0 ^ k1 ^ 0x1BD11BDAu;
#define RND(r) { x0 += x1; x1 = rotl32(x1, r); x1 ^= x0; }
    x0 += ks0; x1 += ks1;
    RND(13) RND(15) RND(26) RND(6)   x0 += ks1; x1 += ks2 + 1u;
    RND(17) RND(29) RND(16) RND(24)  x0 += ks2; x1 += ks0 + 2u;
    RND(13) RND(15) RND(26) RND(6)   x0 += ks0; x1 += ks1 + 3u;
    RND(17) RND(29) RND(16) RND(24)  x0 += ks1; x1 += ks2 + 4u;
    RND(13) RND(15) RND(26) RND(6)   x0 += ks2; x1 += ks0 + 5u;
#undef RND
    o0 = x0; o1 = x1;
}

// starts[g] = jax.random.randint(key(1), (80,), 0, 1024)[g], partitionable threefry
__device__ __forceinline__ int jax_start(int gidx) {
    uint32_t c0, c1, o0, o1;
    tf2x32(0u, 1u, 0u, 1u, c0, c1);
    tf2x32(c0, c1, 0u, (uint32_t)gidx, o0, o1);
    return (int)((o0 ^ o1) & 1023u);
}

// ---------------- grid barrier with fused any-moved reduction ----------------
__device__ __forceinline__ int grid_barrier_any(int moved) {
    __shared__ int sNotdone;
    __syncthreads();
    if (threadIdx.x == 0) {
        volatile unsigned int* vgen = &g_bar_gen;
        unsigned int gen = *vgen;
        __threadfence();
        unsigned int ticket = atomicAdd(&g_bar_count, 1u + (moved ? 0x10000u : 0u));
        if ((ticket & 0xFFFFu) == NGROUP - 1) {
            unsigned int movedCnt = (ticket >> 16) + (moved ? 1u : 0u);
            g_bar_count = 0u;
            g_notdone = (movedCnt != 0u) ? 1 : 0;
            __threadfence();
            atomicAdd(&g_bar_gen, 1u);
        } else {
            while (*vgen == gen) { __nanosleep(32); }
        }
        __threadfence();
        sNotdone = *((volatile int*)&g_notdone);
    }
    __syncthreads();
    return sNotdone;
}

__device__ __forceinline__ float sq3(float a, float b, float c) {
    // ((a*a + b*b) + c*c), non-fused (reference-critical math)
    return __fadd_rn(__fadd_rn(__fmul_rn(a, a), __fmul_rn(b, b)), __fmul_rn(c, c));
}

// ---------------- main persistent kernel: FPS + k-means + score ----------------
__global__ void __launch_bounds__(NTHR, 1)
kmeans_kernel(const float* __restrict__ pos, float* __restrict__ out, int out_size) {
    __shared__ float4   sP[NPG];          // points                             16384 B
    __shared__ float4   sC[MCENT];        // centroids as (-2x,-2y,-2z,|c|^2)    8192 B
    __shared__ uint8_t  whist[32][MCENT]; // rows 0-15: A-points, 16-31: B      16384 B
    __shared__ uint16_t sortIdx[NPG];     // cluster-sorted point indices        2048 B
    __shared__ uint16_t sCnt[MCENT];
    __shared__ uint16_t sOff[MCENT];
    __shared__ uint32_t sWsum[16];
    __shared__ uint32_t redV[2][16];
    __shared__ uint32_t redI[2][16];
    __shared__ float    redF[16];
    __shared__ float    sScore;
    __shared__ int      sStart;

    const int g = blockIdx.x;
    const int t = threadIdx.x;
    const int b = g & (BEX - 1);           // group g = r*B + b  ->  example b
    const float* pb = pos + (size_t)b * NPG * 3;

    // two points per thread: A = t, B = t + 512
    const float pxA = pb[t * 3 + 0], pyA = pb[t * 3 + 1], pzA = pb[t * 3 + 2];
    const float pxB = pb[(t + NTHR) * 3 + 0], pyB = pb[(t + NTHR) * 3 + 1], pzB = pb[(t + NTHR) * 3 + 2];
    sP[t]        = make_float4(pxA, pyA, pzA, 0.f);
    sP[t + NTHR] = make_float4(pxB, pyB, pzB, 0.f);
    if (t == NTHR - 1) sStart = jax_start(g);    // merged starts kernel (exact)
    __syncthreads();

    const int wid = t >> 5, lane = t & 31;

    // ================= FPS init (R9-identical math; ballot-based stage-1 index) =================
    int last = sStart;
    float mindA = FINF;
    float mindB = FINF;
    for (int k = 0; k < MCENT; ++k) {
        float4 q = sP[last];                   // uniform broadcast
        if (t == 0)
            sC[k] = make_float4(__fmul_rn(-2.0f, q.x), __fmul_rn(-2.0f, q.y),
                                __fmul_rn(-2.0f, q.z), sq3(q.x, q.y, q.z));
        {
            float dx = __fsub_rn(pxA, q.x), dy = __fsub_rn(pyA, q.y), dz = __fsub_rn(pzA, q.z);
            mindA = fminf(mindA, sq3(dx, dy, dz));
        }
        {
            float dx = __fsub_rn(pxB, q.x), dy = __fsub_rn(pyB, q.y), dz = __fsub_rn(pzB, q.z);
            mindB = fminf(mindB, sq3(dx, dy, dz));
        }
        // argmax(mind), FIRST-index tie-break.
        // Per-lane candidate prefers A on ties (smaller idx). Min global index among
        // max-achieving lanes: A-type indices (t) all precede B-type (t+512), so pick
        // the lowest A-type max lane if any, else the lowest B-type max lane.
        uint32_t bA = __float_as_uint(mindA);  // positive-float bits monotonic
        uint32_t bB = __float_as_uint(mindB);
        uint32_t bmask = __ballot_sync(0xffffffffu, bB > bA);   // lanes whose candidate is B
        uint32_t val = (bB > bA) ? bB : bA;
        uint32_t wm  = __reduce_max_sync(0xffffffffu, val);
        uint32_t mk  = __ballot_sync(0xffffffffu, val == wm);
        uint32_t mkA = mk & ~bmask;
        uint32_t pick = mkA ? mkA : mk;
        int src = __ffs(pick) - 1;
        uint32_t wix = (uint32_t)((wid << 5) + src) + (mkA ? 0u : (uint32_t)NTHR);
        int par = k & 1;
        if (lane == 0) { redV[par][wid] = wm; redI[par][wid] = wix; }
        __syncthreads();
        uint32_t v  = (lane < 16) ? redV[par][lane] : 0u;
        uint32_t gm = __reduce_max_sync(0xffffffffu, v);
        uint32_t cm = (lane < 16 && v == gm) ? redI[par][lane] : 0xFFFFu;
        last = (int)__reduce_min_sync(0xffffffffu, cm);   // smallest global index
    }
    __syncthreads();

    // ================= k-means loop (global lockstep; R9-verbatim) =================
    int bjA = 0, bjB = 0;
    for (int iter = 0; iter < MAXIT; ++iter) {
        // ---- assign: argmin_j (c2 + px*(-2cx) + py*(-2cy) + pz*(-2cz)) ----
        float bestA = FINF;
        float bestB = FINF;
        bjA = 0; bjB = 0;
        #pragma unroll 8
        for (int j = 0; j < MCENT; ++j) {
            float4 c = sC[j];
            float aA = __fmaf_rn(pzA, c.z, __fmaf_rn(pyA, c.y, __fmaf_rn(pxA, c.x, c.w)));
            float aB = __fmaf_rn(pzB, c.z, __fmaf_rn(pyB, c.y, __fmaf_rn(pxB, c.x, c.w)));
            if (aA < bestA) { bestA = aA; bjA = j; }   // strict '<' keeps first index
            if (aB < bestB) { bestB = aB; bjB = j; }
        }

        // ---- deterministic stable counting sort of points by cluster ----
        ((uint4*)whist)[t * 2]     = make_uint4(0u, 0u, 0u, 0u);   // zero 16KB
        ((uint4*)whist)[t * 2 + 1] = make_uint4(0u, 0u, 0u, 0u);
        __syncthreads();

        // per-warp stable ranks + per-warp histograms (A rows 0-15, B rows 16-31)
        uint32_t below = (1u << lane) - 1u;
        uint32_t mmA = __match_any_sync(0xffffffffu, (uint32_t)bjA);
        int riwA = __popc(mmA & below);
        if (riwA == 0) whist[wid][bjA] = (uint8_t)__popc(mmA);
        uint32_t mmB = __match_any_sync(0xffffffffu, (uint32_t)bjB);
        int riwB = __popc(mmB & below);
        if (riwB == 0) whist[16 + wid][bjB] = (uint8_t)__popc(mmB);
        __syncthreads();

        // per-cluster exclusive prefix over the 32 rows (in place) + counts
        uint32_t run = 0;
        #pragma unroll
        for (int w = 0; w < 32; ++w) {
            uint32_t v = whist[w][t];
            whist[w][t] = (uint8_t)run;
            run += v;
        }
        sCnt[t] = (uint16_t)run;

        // block-wide exclusive prefix sum over the 512 counts (16 warps)
        uint32_t x = run;
        #pragma unroll
        for (int o = 1; o < 32; o <<= 1) {
            uint32_t y = __shfl_up_sync(0xffffffffu, x, o);
            if (lane >= o) x += y;
        }
        uint32_t exclInWarp = x - run;
        if (lane == 31) sWsum[wid] = x;
        __syncthreads();
        if (wid == 0) {
            uint32_t wv = (lane < 16) ? sWsum[lane] : 0u;
            uint32_t xx = wv;
            #pragma unroll
            for (int o = 1; o < 16; o <<= 1) {
                uint32_t y = __shfl_up_sync(0xffffffffu, xx, o);
                if (lane >= o) xx += y;
            }
            if (lane < 16) sWsum[lane] = xx - wv;
        }
        __syncthreads();
        sOff[t] = (uint16_t)(sWsum[wid] + exclInWarp);
        __syncthreads();

        // scatter point indices; ascending-index order preserved per cluster
        {
            uint32_t rkA = (uint32_t)sOff[bjA] + whist[wid][bjA] + (uint32_t)riwA;
            sortIdx[rkA] = (uint16_t)t;
            uint32_t rkB = (uint32_t)sOff[bjB] + whist[16 + wid][bjB] + (uint32_t)riwB;
            sortIdx[rkB] = (uint16_t)(t + NTHR);
        }
        __syncthreads();

        // per-cluster ordered fold + centroid update + convergence
        int moved = 0;
        {
            uint32_t n = sCnt[t], base = sOff[t];
            float sx = 0.f, sy = 0.f, sz = 0.f;
            for (uint32_t k2 = 0; k2 < n; ++k2) {
                float4 p = sP[sortIdx[base + k2]];
                sx = __fadd_rn(sx, p.x);
                sy = __fadd_rn(sy, p.y);
                sz = __fadd_rn(sz, p.z);
            }
            float4 cs = sC[t];
            float ocx = __fmul_rn(-0.5f, cs.x);   // exact recovery
            float ocy = __fmul_rn(-0.5f, cs.y);
            float ocz = __fmul_rn(-0.5f, cs.z);
            float cntf = (float)n;
            float nx, ny, nz;
            if (n > 0) {
                nx = __fdiv_rn(sx, cntf); ny = __fdiv_rn(sy, cntf); nz = __fdiv_rn(sz, cntf);
            } else {
                nx = ocx; ny = ocy; nz = ocz;
            }
            float dx = __fsub_rn(ocx, nx), dy = __fsub_rn(ocy, ny), dz = __fsub_rn(ocz, nz);
            moved = !(sqrtf(sq3(dx, dy, dz)) < TOLF);
            sC[t] = make_float4(__fmul_rn(-2.0f, nx), __fmul_rn(-2.0f, ny),
                                __fmul_rn(-2.0f, nz), sq3(nx, ny, nz));
        }
        int any = __syncthreads_or(moved);
        int notdone = grid_barrier_any(any);
        if (!notdone) break;   // all blocks agree -> same iteration count everywhere
    }

    // ================= score: L1 to assigned (final) centroids =================
    {
        float4 ca = sC[bjA];
        float cax = __fmul_rn(-0.5f, ca.x), cay = __fmul_rn(-0.5f, ca.y), caz = __fmul_rn(-0.5f, ca.z);
        float4 cb = sC[bjB];
        float cbx = __fmul_rn(-0.5f, cb.x), cby = __fmul_rn(-0.5f, cb.y), cbz = __fmul_rn(-0.5f, cb.z);
        float s = fabsf(pxA - cax) + fabsf(pyA - cay) + fabsf(pzA - caz)
                + fabsf(pxB - cbx) + fabsf(pyB - cby) + fabsf(pzB - cbz);
        #pragma unroll
        for (int off = 16; off > 0; off >>= 1)
            s += __shfl_down_sync(0xffffffffu, s, off);
        if (lane == 0) redF[wid] = s;
        __syncthreads();
        if (wid == 0) {
            float v = (lane < 16) ? redF[lane] : 0.f;
            #pragma unroll
            for (int off = 8; off > 0; off >>= 1)
                v += __shfl_down_sync(0xffffffffu, v, off);
            if (lane == 0) sScore = v;
        }
        __syncthreads();
    }

    // ================= outputs: [classification | centroids | scores] =================
    int ci = g * NPG + t;
    if (ci < out_size) out[ci] = (float)bjA;
    int ci2 = g * NPG + NTHR + t;
    if (ci2 < out_size) out[ci2] = (float)bjB;
    {
        int base = NGROUP * NPG + g * (MCENT * 3) + t * 3;
        if (base + 2 < out_size) {
            float4 cs = sC[t];
            out[base + 0] = __fmul_rn(-0.5f, cs.x);
            out[base + 1] = __fmul_rn(-0.5f, cs.y);
            out[base + 2] = __fmul_rn(-0.5f, cs.z);
        }
    }
    if (t == 0) {
        int si = NGROUP * NPG + NGROUP * MCENT * 3 + g;
        if (si < out_size) out[si] = sScore;
    }
}

extern "C" void kernel_launch(void* const* d_in, const int* in_sizes, int n_in,
                              void* d_out, int out_size) {
    const float* pos = (const float*)d_in[0];
    kmeans_kernel<<<NGROUP, NTHR>>>(pos, (float*)d_out, out_size);
}

// round 15
// speedup vs baseline: 2.2314x; 1.0976x over previous
#include <cuda_runtime.h>
#include <cstdint>

#define NGROUP 80
#define BEX 8
#define NPG 1024
#define MCENT 512
#define NTHR 512
#define MAXIT 300
#define TOLF 1e-3f
#define FINF __int_as_float(0x7f800000)

// ---------------- device globals (no allocation allowed) ----------------
__device__ unsigned int g_bar_count;   // packed: low 16 = arrivals, high = moved count; returns to 0
__device__ unsigned int g_bar_gen;     // monotonically increasing across replays (safe)
__device__ int g_notdone;              // published by last arriver before gen flip

// ---------------- threefry2x32 (exact JAX PRNG, partitionable scheme) ----------------
__device__ __forceinline__ uint32_t rotl32(uint32_t x, int d) { return (x << d) | (x >> (32 - d)); }

__device__ __forceinline__ void tf2x32(uint32_t k0, uint32_t k1, uint32_t x0, uint32_t x1,
                                       uint32_t& o0, uint32_t& o1) {
    uint32_t ks0 = k0, ks1 = k1, ks2 = k0 ^ k1 ^ 0x1BD11BDAu;
#define RND(r) { x0 += x1; x1 = rotl32(x1, r); x1 ^= x0; }
    x0 += ks0; x1 += ks1;
    RND(13) RND(15) RND(26) RND(6)   x0 += ks1; x1 += ks2 + 1u;
    RND(17) RND(29) RND(16) RND(24)  x0 += ks2; x1 += ks0 + 2u;
    RND(13) RND(15) RND(26) RND(6)   x0 += ks0; x1 += ks1 + 3u;
    RND(17) RND(29) RND(16) RND(24)  x0 += ks1; x1 += ks2 + 4u;
    RND(13) RND(15) RND(26) RND(6)   x0 += ks2; x1 += ks0 + 5u;
#undef RND
    o0 = x0; o1 = x1;
}

// starts[g] = jax.random.randint(key(1), (80,), 0, 1024)[g], partitionable threefry
__device__ __forceinline__ int jax_start(int gidx) {
    uint32_t c0, c1, o0, o1;
    tf2x32(0u, 1u, 0u, 1u, c0, c1);
    tf2x32(c0, c1, 0u, (uint32_t)gidx, o0, o1);
    return (int)((o0 ^ o1) & 1023u);
}

// ---------------- grid barrier with fused any-moved reduction ----------------
__device__ __forceinline__ int grid_barrier_any(int moved) {
    __shared__ int sNotdone;
    __syncthreads();
    if (threadIdx.x == 0) {
        volatile unsigned int* vgen = &g_bar_gen;
        unsigned int gen = *vgen;
        __threadfence();
        unsigned int ticket = atomicAdd(&g_bar_count, 1u + (moved ? 0x10000u : 0u));
        if ((ticket & 0xFFFFu) == NGROUP - 1) {
            unsigned int movedCnt = (ticket >> 16) + (moved ? 1u : 0u);
            g_bar_count = 0u;
            g_notdone = (movedCnt != 0u) ? 1 : 0;
            __threadfence();
            atomicAdd(&g_bar_gen, 1u);
        } else {
            while (*vgen == gen) { __nanosleep(32); }
        }
        __threadfence();
        sNotdone = *((volatile int*)&g_notdone);
    }
    __syncthreads();
    return sNotdone;
}

__device__ __forceinline__ float sq3(float a, float b, float c) {
    // ((a*a + b*b) + c*c), non-fused (reference-critical math)
    return __fadd_rn(__fadd_rn(__fmul_rn(a, a), __fmul_rn(b, b)), __fmul_rn(c, c));
}

// ---------------- main persistent kernel: FPS + k-means + score ----------------
__global__ void __launch_bounds__(NTHR, 1)
kmeans_kernel(const float* __restrict__ pos, float* __restrict__ out, int out_size) {
    __shared__ float4   sP[NPG];          // points                             16384 B
    __shared__ float4   sC[MCENT];        // centroids as (-2x,-2y,-2z,|c|^2)    8192 B
    __shared__ uint8_t  whist[32][MCENT]; // rows 0-15: A-points, 16-31: B      16384 B
    __shared__ uint16_t sortIdx[NPG];     // cluster-sorted point indices        2048 B
    __shared__ uint16_t sCnt[MCENT];
    __shared__ uint16_t sOff[MCENT];
    __shared__ uint32_t sWsum[16];
    __shared__ uint2    redVI[2][16];     // interleaved {val, idx} per warp, per parity
    __shared__ float    redF[16];
    __shared__ float    sScore;
    __shared__ int      sStart;

    const int g = blockIdx.x;
    const int t = threadIdx.x;
    const int b = g & (BEX - 1);           // group g = r*B + b  ->  example b
    const float* pb = pos + (size_t)b * NPG * 3;

    // two points per thread: A = t, B = t + 512
    const float pxA = pb[t * 3 + 0], pyA = pb[t * 3 + 1], pzA = pb[t * 3 + 2];
    const float pxB = pb[(t + NTHR) * 3 + 0], pyB = pb[(t + NTHR) * 3 + 1], pzB = pb[(t + NTHR) * 3 + 2];
    sP[t]        = make_float4(pxA, pyA, pzA, 0.f);
    sP[t + NTHR] = make_float4(pxB, pyB, pzB, 0.f);
    if (t == NTHR - 1) sStart = jax_start(g);    // merged starts kernel (exact)
    __syncthreads();

    const int wid = t >> 5, lane = t & 31;

    // ================= FPS init (R9-identical math & reductions) =================
    int last = sStart;
    float mindA = FINF;
    float mindB = FINF;
    for (int k = 0; k < MCENT; ++k) {
        float4 q = sP[last];                   // uniform broadcast
        if (t == 0)
            sC[k] = make_float4(__fmul_rn(-2.0f, q.x), __fmul_rn(-2.0f, q.y),
                                __fmul_rn(-2.0f, q.z), sq3(q.x, q.y, q.z));
        {
            float dx = __fsub_rn(pxA, q.x), dy = __fsub_rn(pyA, q.y), dz = __fsub_rn(pzA, q.z);
            mindA = fminf(mindA, sq3(dx, dy, dz));
        }
        {
            float dx = __fsub_rn(pxB, q.x), dy = __fsub_rn(pyB, q.y), dz = __fsub_rn(pzB, q.z);
            mindB = fminf(mindB, sq3(dx, dy, dz));
        }
        // argmax(mind), FIRST-index tie-break: value-max + min-index-among-max.
        uint32_t bA = __float_as_uint(mindA);  // positive-float bits monotonic
        uint32_t bB = __float_as_uint(mindB);
        uint32_t val = (bB > bA) ? bB : bA;
        uint32_t idx = (bB > bA) ? (uint32_t)(t + NTHR) : (uint32_t)t;  // tie -> A (smaller idx)
        uint32_t wm  = __reduce_max_sync(0xffffffffu, val);
        uint32_t cnd = (val == wm) ? idx : 0xFFFFu;
        uint32_t wix = __reduce_min_sync(0xffffffffu, cnd);
        int par = k & 1;
        if (lane == 0) redVI[par][wid] = make_uint2(wm, wix);   // one STS.64
        __syncthreads();
        uint2 vi = (lane < 16) ? redVI[par][lane] : make_uint2(0u, 0xFFFFu);  // one LDS.64
        uint32_t gm = __reduce_max_sync(0xffffffffu, vi.x);
        uint32_t cm = (vi.x == gm) ? vi.y : 0xFFFFu;
        last = (int)__reduce_min_sync(0xffffffffu, cm);   // smallest global index
    }
    __syncthreads();

    // ================= k-means loop (global lockstep; R9-verbatim) =================
    int bjA = 0, bjB = 0;
    for (int iter = 0; iter < MAXIT; ++iter) {
        // ---- assign: argmin_j (c2 + px*(-2cx) + py*(-2cy) + pz*(-2cz)) ----
        float bestA = FINF;
        float bestB = FINF;
        bjA = 0; bjB = 0;
        #pragma unroll 8
        for (int j = 0; j < MCENT; ++j) {
            float4 c = sC[j];
            float aA = __fmaf_rn(pzA, c.z, __fmaf_rn(pyA, c.y, __fmaf_rn(pxA, c.x, c.w)));
            float aB = __fmaf_rn(pzB, c.z, __fmaf_rn(pyB, c.y, __fmaf_rn(pxB, c.x, c.w)));
            if (aA < bestA) { bestA = aA; bjA = j; }   // strict '<' keeps first index
            if (aB < bestB) { bestB = aB; bjB = j; }
        }

        // ---- deterministic stable counting sort of points by cluster ----
        ((uint4*)whist)[t * 2]     = make_uint4(0u, 0u, 0u, 0u);   // zero 16KB
        ((uint4*)whist)[t * 2 + 1] = make_uint4(0u, 0u, 0u, 0u);
        __syncthreads();

        // per-warp stable ranks + per-warp histograms (A rows 0-15, B rows 16-31)
        uint32_t below = (1u << lane) - 1u;
        uint32_t mmA = __match_any_sync(0xffffffffu, (uint32_t)bjA);
        int riwA = __popc(mmA & below);
        if (riwA == 0) whist[wid][bjA] = (uint8_t)__popc(mmA);
        uint32_t mmB = __match_any_sync(0xffffffffu, (uint32_t)bjB);
        int riwB = __popc(mmB & below);
        if (riwB == 0) whist[16 + wid][bjB] = (uint8_t)__popc(mmB);
        __syncthreads();

        // per-cluster exclusive prefix over the 32 rows (in place) + counts
        uint32_t run = 0;
        #pragma unroll
        for (int w = 0; w < 32; ++w) {
            uint32_t v = whist[w][t];
            whist[w][t] = (uint8_t)run;
            run += v;
        }
        sCnt[t] = (uint16_t)run;

        // block-wide exclusive prefix sum over the 512 counts (16 warps)
        uint32_t x = run;
        #pragma unroll
        for (int o = 1; o < 32; o <<= 1) {
            uint32_t y = __shfl_up_sync(0xffffffffu, x, o);
            if (lane >= o) x += y;
        }
        uint32_t exclInWarp = x - run;
        if (lane == 31) sWsum[wid] = x;
        __syncthreads();
        if (wid == 0) {
            uint32_t wv = (lane < 16) ? sWsum[lane] : 0u;
            uint32_t xx = wv;
            #pragma unroll
            for (int o = 1; o < 16; o <<= 1) {
                uint32_t y = __shfl_up_sync(0xffffffffu, xx, o);
                if (lane >= o) xx += y;
            }
            if (lane < 16) sWsum[lane] = xx - wv;
        }
        __syncthreads();
        sOff[t] = (uint16_t)(sWsum[wid] + exclInWarp);
        __syncthreads();

        // scatter point indices; ascending-index order preserved per cluster
        {
            uint32_t rkA = (uint32_t)sOff[bjA] + whist[wid][bjA] + (uint32_t)riwA;
            sortIdx[rkA] = (uint16_t)t;
            uint32_t rkB = (uint32_t)sOff[bjB] + whist[16 + wid][bjB] + (uint32_t)riwB;
            sortIdx[rkB] = (uint16_t)(t + NTHR);
        }
        __syncthreads();

        // per-cluster ordered fold + centroid update + convergence
        int moved = 0;
        {
            uint32_t n = sCnt[t], base = sOff[t];
            float sx = 0.f, sy = 0.f, sz = 0.f;
            for (uint32_t k2 = 0; k2 < n; ++k2) {
                float4 p = sP[sortIdx[base + k2]];
                sx = __fadd_rn(sx, p.x);
                sy = __fadd_rn(sy, p.y);
                sz = __fadd_rn(sz, p.z);
            }
            float4 cs = sC[t];
            float ocx = __fmul_rn(-0.5f, cs.x);   // exact recovery
            float ocy = __fmul_rn(-0.5f, cs.y);
            float ocz = __fmul_rn(-0.5f, cs.z);
            float cntf = (float)n;
            float nx, ny, nz;
            if (n > 0) {
                nx = __fdiv_rn(sx, cntf); ny = __fdiv_rn(sy, cntf); nz = __fdiv_rn(sz, cntf);
            } else {
                nx = ocx; ny = ocy; nz = ocz;
            }
            float dx = __fsub_rn(ocx, nx), dy = __fsub_rn(ocy, ny), dz = __fsub_rn(ocz, nz);
            moved = !(sqrtf(sq3(dx, dy, dz)) < TOLF);
            sC[t] = make_float4(__fmul_rn(-2.0f, nx), __fmul_rn(-2.0f, ny),
                                __fmul_rn(-2.0f, nz), sq3(nx, ny, nz));
        }
        int any = __syncthreads_or(moved);
        int notdone = grid_barrier_any(any);
        if (!notdone) break;   // all blocks agree -> same iteration count everywhere
    }

    // ================= score: L1 to assigned (final) centroids =================
    {
        float4 ca = sC[bjA];
        float cax = __fmul_rn(-0.5f, ca.x), cay = __fmul_rn(-0.5f, ca.y), caz = __fmul_rn(-0.5f, ca.z);
        float4 cb = sC[bjB];
        float cbx = __fmul_rn(-0.5f, cb.x), cby = __fmul_rn(-0.5f, cb.y), cbz = __fmul_rn(-0.5f, cb.z);
        float s = fabsf(pxA - cax) + fabsf(pyA - cay) + fabsf(pzA - caz)
                + fabsf(pxB - cbx) + fabsf(pyB - cby) + fabsf(pzB - cbz);
        #pragma unroll
        for (int off = 16; off > 0; off >>= 1)
            s += __shfl_down_sync(0xffffffffu, s, off);
        if (lane == 0) redF[wid] = s;
        __syncthreads();
        if (wid == 0) {
            float v = (lane < 16) ? redF[lane] : 0.f;
            #pragma unroll
            for (int off = 8; off > 0; off >>= 1)
                v += __shfl_down_sync(0xffffffffu, v, off);
            if (lane == 0) sScore = v;
        }
        __syncthreads();
    }

    // ================= outputs: [classification | centroids | scores] =================
    int ci = g * NPG + t;
    if (ci < out_size) out[ci] = (float)bjA;
    int ci2 = g * NPG + NTHR + t;
    if (ci2 < out_size) out[ci2] = (float)bjB;
    {
        int base = NGROUP * NPG + g * (MCENT * 3) + t * 3;
        if (base + 2 < out_size) {
            float4 cs = sC[t];
            out[base + 0] = __fmul_rn(-0.5f, cs.x);
            out[base + 1] = __fmul_rn(-0.5f, cs.y);
            out[base + 2] = __fmul_rn(-0.5f, cs.z);
        }
    }
    if (t == 0) {
        int si = NGROUP * NPG + NGROUP * MCENT * 3 + g;
        if (si < out_size) out[si] = sScore;
    }
}

extern "C" void kernel_launch(void* const* d_in, const int* in_sizes, int n_in,
                              void* d_out, int out_size) {
    const float* pos = (const float*)d_in[0];
    kmeans_kernel<<<NGROUP, NTHR>>>(pos, (float*)d_out, out_size);
}